// round 2
// baseline (speedup 1.0000x reference)
#include <cuda_runtime.h>
#include <cuda_bf16.h>
#include <math.h>

// ---------------- problem constants ----------------
#define BATCH   8192
#define SEG     3200
#define NFFT    512
#define HOP     160
#define NFREQ   257
#define NFRM    17
#define SD      4369          // NFREQ*NFRM
#define NB      128
#define LAM     0.5f
#define ITERS   50

#define PI_F 3.14159265358979f

// ---------------- scratch (no allocation allowed) ----------------
__device__ float g_spec[(size_t)BATCH * SD];   // T-major: [b][t*257+f]  (~143 MB)
__device__ float g_stats[BATCH * 2];           // mean, invstd
__device__ float g_b[(size_t)BATCH * NB];
__device__ float g_gram[NB * NB];              // D D^T - I
__device__ float g_Dp[(size_t)NB * SD];        // D permuted to T-major
__device__ float g_sumD[NB];

// ---------------- D permute (F-major -> T-major) + row sums ----------------
__global__ void permuted_kernel(const float* __restrict__ D) {
    int j = blockIdx.x;
    int tid = threadIdx.x;
    const float* src = D + (size_t)j * SD;
    float* dst = g_Dp + (size_t)j * SD;
    float s = 0.f;
    for (int k = tid; k < SD; k += 256) {
        int t = k / NFREQ;
        int f = k - t * NFREQ;
        float v = src[f * NFRM + t];
        dst[k] = v;
        s += v;
    }
    __shared__ float red[256];
    red[tid] = s; __syncthreads();
    for (int o = 128; o > 0; o >>= 1) {
        if (tid < o) red[tid] += red[tid + o];
        __syncthreads();
    }
    if (tid == 0) g_sumD[j] = red[0];
}

// ---------------- gram = D D^T - I  (64 blocks of 16x16 outputs) ----------------
__global__ void gram_kernel(const float* __restrict__ D) {
    int ti = (blockIdx.x >> 3) * 16;
    int tj = (blockIdx.x & 7) * 16;
    int tid = threadIdx.x;            // 256
    int li = tid >> 4, lj = tid & 15;
    __shared__ float shi[16][65];
    __shared__ float shj[16][65];
    float acc = 0.f;
    int kk = tid & 63, r = tid >> 6;  // r in 0..3
    for (int k0 = 0; k0 < SD; k0 += 64) {
        int k = k0 + kk;
        bool ok = (k < SD);
        #pragma unroll
        for (int rr = 0; rr < 4; rr++) {
            int row = r + rr * 4;
            shi[row][kk] = ok ? D[(size_t)(ti + row) * SD + k] : 0.f;
            shj[row][kk] = ok ? D[(size_t)(tj + row) * SD + k] : 0.f;
        }
        __syncthreads();
        #pragma unroll 16
        for (int q = 0; q < 64; q++) acc += shi[li][q] * shj[lj][q];
        __syncthreads();
    }
    int i = ti + li, j = tj + lj;
    g_gram[i * NB + j] = acc - (i == j ? 1.f : 0.f);
}

// ---------------- STFT: 512-pt real FFT via packed 256-pt complex FFT ----------------
// one frame per 128-thread block; grid = (17, 8192)
__global__ void stft_kernel(const float* __restrict__ audio) {
    const int t = blockIdx.x;
    const int b = blockIdx.y;
    const int tid = threadIdx.x;     // 128
    __shared__ float sre[256];
    __shared__ float sim[256];

    const float* xp = audio + (size_t)b * SEG + t * HOP;
    const float W0 = 2.f * PI_F / (float)NFFT;

    // load + periodic-hann window + pack pairs + bit-reverse store
    #pragma unroll
    for (int p = tid; p < 256; p += 128) {
        float2 v = *(const float2*)(xp + 2 * p);
        int n0 = 2 * p;
        float w0 = 0.5f - 0.5f * __cosf(W0 * (float)n0);
        float w1 = 0.5f - 0.5f * __cosf(W0 * (float)(n0 + 1));
        int rix = __brev((unsigned)p) >> 24;   // 8-bit reverse
        sre[rix] = v.x * w0;
        sim[rix] = v.y * w1;
    }
    __syncthreads();

    // 8 radix-2 DIT stages (128 butterflies per stage, one per thread)
    #pragma unroll
    for (int s = 0; s < 8; s++) {
        int half = 1 << s;
        int pos = tid & (half - 1);
        int i0 = ((tid >> s) << (s + 1)) + pos;
        int i1 = i0 + half;
        float ang = -PI_F * (float)pos / (float)half;
        float wi, wr;
        __sincosf(ang, &wi, &wr);
        float ar = sre[i0], ai = sim[i0];
        float br = sre[i1], bi = sim[i1];
        float tr = br * wr - bi * wi;
        float ti2 = br * wi + bi * wr;
        sre[i0] = ar + tr;  sim[i0] = ai + ti2;
        sre[i1] = ar - tr;  sim[i1] = ai - ti2;
        __syncthreads();
    }

    // unpack real-FFT halves + magnitude; spec layout [b][t*257+f]
    float* out = g_spec + (size_t)b * SD + t * NFREQ;
    int k = tid;
    if (k == 0) {
        float re0 = sre[0], im0 = sim[0];
        out[0]   = fabsf(re0 + im0);
        out[256] = fabsf(re0 - im0);
        out[128] = sqrtf(sre[128] * sre[128] + sim[128] * sim[128]);
    } else {
        int mk = 256 - k;
        float zr = sre[k], zi = sim[k];
        float yr = sre[mk], yi = sim[mk];
        float er  = 0.5f * (zr + yr);
        float ei  = 0.5f * (zi - yi);
        float orr = 0.5f * (zi + yi);
        float oi  = -0.5f * (zr - yr);
        float ang = -PI_F * (float)k / 256.f;
        float ci, cr;
        __sincosf(ang, &ci, &cr);
        // X_k = E + W^k O
        float xr = er + cr * orr - ci * oi;
        float xi = ei + cr * oi + ci * orr;
        out[k] = sqrtf(xr * xr + xi * xi);
        // X_{256-k}: E' = (er, -ei); O' = (orr, -oi); W^{256-k} = (-cr, ci)
        float xr2 = er + (-cr) * orr - ci * (-oi);
        float xi2 = -ei + (-cr) * (-oi) + ci * orr;
        out[mk] = sqrtf(xr2 * xr2 + xi2 * xi2);
    }
}

// ---------------- per-sample mean / inv(std+1e-8), unbiased std ----------------
__global__ void stats_kernel() {
    int b = blockIdx.x;
    int tid = threadIdx.x;            // 256
    const float* row = g_spec + (size_t)b * SD;
    float s = 0.f, s2 = 0.f;
    for (int k = tid; k < SD; k += 256) {
        float v = row[k];
        s += v; s2 += v * v;
    }
    __shared__ float rs[256], r2[256];
    rs[tid] = s; r2[tid] = s2; __syncthreads();
    for (int o = 128; o > 0; o >>= 1) {
        if (tid < o) { rs[tid] += rs[tid + o]; r2[tid] += r2[tid + o]; }
        __syncthreads();
    }
    if (tid == 0) {
        float mean = rs[0] / (float)SD;
        float var = (r2[0] - (float)SD * mean * mean) / (float)(SD - 1);
        float sd = sqrtf(fmaxf(var, 0.f));
        g_stats[2 * b]     = mean;
        g_stats[2 * b + 1] = 1.f / (sd + 1e-8f);
    }
}

// ---------------- b = ((spec - mean)*invstd) @ D^T ----------------
// tile: 64 samples x 128 bases per block; 128 blocks, 256 threads
#define KC 32
__global__ void __launch_bounds__(256) bgemm_kernel() {
    __shared__ float sA[KC][68];    // [kk][s]
    __shared__ float sB[KC][132];   // [kk][j]
    int tid = threadIdx.x;
    int s0 = blockIdx.x * 64;
    int kk = tid & 31, rg = tid >> 5;
    int sl0 = (tid >> 4) * 4;
    int j0  = (tid & 15) * 8;
    float acc[4][8] = {};

    for (int k0 = 0; k0 < SD; k0 += KC) {
        int k = k0 + kk;
        bool ok = (k < SD);
        #pragma unroll
        for (int m = 0; m < 8; m++) {
            int ss = rg * 8 + m;
            sA[kk][ss] = ok ? g_spec[(size_t)(s0 + ss) * SD + k] : 0.f;
        }
        #pragma unroll
        for (int m = 0; m < 16; m++) {
            int j = rg * 16 + m;
            sB[kk][j] = ok ? g_Dp[(size_t)j * SD + k] : 0.f;
        }
        __syncthreads();
        #pragma unroll 8
        for (int q = 0; q < KC; q++) {
            float4 a  = *(const float4*)&sA[q][sl0];
            float4 b0 = *(const float4*)&sB[q][j0];
            float4 b1 = *(const float4*)&sB[q][j0 + 4];
            float av[4] = {a.x, a.y, a.z, a.w};
            float gv[8] = {b0.x, b0.y, b0.z, b0.w, b1.x, b1.y, b1.z, b1.w};
            #pragma unroll
            for (int ii = 0; ii < 4; ii++)
                #pragma unroll
                for (int jj = 0; jj < 8; jj++)
                    acc[ii][jj] += av[ii] * gv[jj];
        }
        __syncthreads();
    }
    #pragma unroll
    for (int ii = 0; ii < 4; ii++) {
        int s = s0 + sl0 + ii;
        float mean = g_stats[2 * s], inv = g_stats[2 * s + 1];
        #pragma unroll
        for (int jj = 0; jj < 8; jj++) {
            int j = j0 + jj;
            g_b[(size_t)s * NB + j] = (acc[ii][jj] - mean * g_sumD[j]) * inv;
        }
    }
}

// ---------------- LCA: 50 iterations, gram in shared, u/b in registers ----------------
// tile: 64 samples per block; 128 blocks, 256 threads, thread tile 4x8
__global__ void __launch_bounds__(256) lca_kernel(float* __restrict__ out) {
    extern __shared__ float smem[];
    float* sG = smem;                  // [128][132]
    float* sa = smem + 128 * 132;      // [64][132]
    int tid = threadIdx.x;
    int s0 = blockIdx.x * 64;

    for (int idx = tid; idx < NB * NB; idx += 256) {
        int i = idx >> 7, j = idx & 127;
        sG[i * 132 + j] = g_gram[idx];
    }

    int sl0 = (tid >> 4) * 4;
    int j0  = (tid & 15) * 8;
    float u[4][8], bb[4][8];
    #pragma unroll
    for (int ii = 0; ii < 4; ii++) {
        const float* bp = g_b + (size_t)(s0 + sl0 + ii) * NB + j0;
        #pragma unroll
        for (int jj = 0; jj < 8; jj++) { bb[ii][jj] = bp[jj]; u[ii][jj] = 0.f; }
    }
    __syncthreads();

    for (int it = 0; it < ITERS; it++) {
        // a = softshrink(u) -> shared
        #pragma unroll
        for (int ii = 0; ii < 4; ii++) {
            float* ap = &sa[(sl0 + ii) * 132 + j0];
            #pragma unroll
            for (int jj = 0; jj < 8; jj++) {
                float x = u[ii][jj];
                float m = fabsf(x) - LAM;
                ap[jj] = (m > 0.f) ? copysignf(m, x) : 0.f;
            }
        }
        __syncthreads();

        float acc[4][8] = {};
        #pragma unroll 2
        for (int i = 0; i < NB; i += 4) {
            float4 a0 = *(const float4*)&sa[(sl0 + 0) * 132 + i];
            float4 a1 = *(const float4*)&sa[(sl0 + 1) * 132 + i];
            float4 a2 = *(const float4*)&sa[(sl0 + 2) * 132 + i];
            float4 a3 = *(const float4*)&sa[(sl0 + 3) * 132 + i];
            float av[4][4] = {{a0.x, a0.y, a0.z, a0.w},
                              {a1.x, a1.y, a1.z, a1.w},
                              {a2.x, a2.y, a2.z, a2.w},
                              {a3.x, a3.y, a3.z, a3.w}};
            #pragma unroll
            for (int q = 0; q < 4; q++) {
                float4 gq0 = *(const float4*)&sG[(i + q) * 132 + j0];
                float4 gq1 = *(const float4*)&sG[(i + q) * 132 + j0 + 4];
                float gv[8] = {gq0.x, gq0.y, gq0.z, gq0.w,
                               gq1.x, gq1.y, gq1.z, gq1.w};
                #pragma unroll
                for (int ii = 0; ii < 4; ii++)
                    #pragma unroll
                    for (int jj = 0; jj < 8; jj++)
                        acc[ii][jj] += av[ii][q] * gv[jj];
            }
        }

        #pragma unroll
        for (int ii = 0; ii < 4; ii++)
            #pragma unroll
            for (int jj = 0; jj < 8; jj++)
                u[ii][jj] += (bb[ii][jj] - u[ii][jj] - acc[ii][jj]) * 0.1f;
        __syncthreads();
    }

    #pragma unroll
    for (int ii = 0; ii < 4; ii++) {
        float* op = out + (size_t)(s0 + sl0 + ii) * NB + j0;
        #pragma unroll
        for (int jj = 0; jj < 8; jj++) {
            float x = u[ii][jj];
            float m = fabsf(x) - LAM;
            op[jj] = (m > 0.f) ? copysignf(m, x) : 0.f;
        }
    }
}

// ---------------- launch ----------------
extern "C" void kernel_launch(void* const* d_in, const int* in_sizes, int n_in,
                              void* d_out, int out_size) {
    const float* audio = (const float*)d_in[0];   // (8192, 3200)
    const float* D     = (const float*)d_in[1];   // (128, 4369)
    float* out = (float*)d_out;                   // (8192, 128)

    static const size_t LCA_SMEM = (128 * 132 + 64 * 132) * sizeof(float); // 101376
    cudaFuncSetAttribute(lca_kernel, cudaFuncAttributeMaxDynamicSharedMemorySize,
                         (int)LCA_SMEM);

    permuted_kernel<<<NB, 256>>>(D);
    gram_kernel<<<64, 256>>>(D);
    stft_kernel<<<dim3(NFRM, BATCH), 128>>>(audio);
    stats_kernel<<<BATCH, 256>>>();
    bgemm_kernel<<<BATCH / 64, 256>>>();
    lca_kernel<<<BATCH / 64, 256, LCA_SMEM>>>(out);
}

// round 4
// speedup vs baseline: 2.0236x; 2.0236x over previous
#include <cuda_runtime.h>
#include <cuda_bf16.h>
#include <math.h>
#include <stdint.h>

#define BATCH 8192
#define SEG   3200
#define NFFT  512
#define HOP   160
#define NFREQ 257
#define NFRM  17
#define SD    4369
#define SDP   4416
#define NCH   69
#define NB    128
#define LAM   0.5f
#define ITERS 50
#define PI_F  3.14159265358979f

__device__ __nv_bfloat16 g_spec_hi[(size_t)BATCH * SDP];
__device__ __nv_bfloat16 g_spec_lo[(size_t)BATCH * SDP];
__device__ __nv_bfloat16 g_Dp_hi[(size_t)NB * SDP];
__device__ __nv_bfloat16 g_Dp_lo[(size_t)NB * SDP];
__device__ float g_gram[NB * NB];
__device__ float g_sumD[NB];
__device__ float g_b[(size_t)BATCH * NB];
__device__ float g_stats[BATCH * 2];
__device__ float g_fstat[(size_t)BATCH * NFRM * 2];

__device__ __forceinline__ void bsplit(float v, __nv_bfloat16& h, __nv_bfloat16& l) {
    h = __float2bfloat16(v);
    l = __float2bfloat16(v - __bfloat162float(h));
}
__device__ __forceinline__ uint32_t bpack(__nv_bfloat16 a, __nv_bfloat16 b) {
    return (uint32_t)__bfloat16_as_ushort(a) | ((uint32_t)__bfloat16_as_ushort(b) << 16);
}
__device__ __forceinline__ float sshrink(float x) {
    float m = fabsf(x) - LAM;
    return (m > 0.f) ? copysignf(m, x) : 0.f;
}
__device__ __forceinline__ void mma16816(float* c, const uint32_t* a, const uint32_t* b) {
    asm volatile("mma.sync.aligned.m16n8k16.row.col.f32.bf16.bf16.f32 "
        "{%0,%1,%2,%3}, {%4,%5,%6,%7}, {%8,%9}, {%0,%1,%2,%3};"
        : "+f"(c[0]), "+f"(c[1]), "+f"(c[2]), "+f"(c[3])
        : "r"(a[0]), "r"(a[1]), "r"(a[2]), "r"(a[3]), "r"(b[0]), "r"(b[1]));
}
__device__ __forceinline__ uint32_t lds32(const char* p) { return *(const uint32_t*)p; }

// ---- D permute (F-major->T-major), bf16 split, row sums, pad zero ----
__global__ void permuted_kernel(const float* __restrict__ D) {
    int j = blockIdx.x, tid = threadIdx.x;
    const float* src = D + (size_t)j * SD;
    float s = 0.f;
    for (int k = tid; k < SDP; k += 256) {
        float v = 0.f;
        if (k < SD) { int t = k / NFREQ, f = k - t * NFREQ; v = src[f * NFRM + t]; s += v; }
        __nv_bfloat16 h, l; bsplit(v, h, l);
        g_Dp_hi[(size_t)j * SDP + k] = h;
        g_Dp_lo[(size_t)j * SDP + k] = l;
    }
    __shared__ float red[256];
    red[tid] = s; __syncthreads();
    for (int o = 128; o > 0; o >>= 1) { if (tid < o) red[tid] += red[tid + o]; __syncthreads(); }
    if (tid == 0) g_sumD[j] = red[0];
}

// ---- gram = D D^T - I (fp32 SIMT, small) ----
__global__ void gram_kernel(const float* __restrict__ D) {
    int ti = (blockIdx.x >> 3) * 16, tj = (blockIdx.x & 7) * 16;
    int tid = threadIdx.x, li = tid >> 4, lj = tid & 15;
    __shared__ float shi[16][65], shj[16][65];
    float acc = 0.f;
    int kk = tid & 63, r = tid >> 6;
    for (int k0 = 0; k0 < SD; k0 += 64) {
        int k = k0 + kk; bool ok = (k < SD);
        #pragma unroll
        for (int rr = 0; rr < 4; rr++) {
            int row = r + rr * 4;
            shi[row][kk] = ok ? D[(size_t)(ti + row) * SD + k] : 0.f;
            shj[row][kk] = ok ? D[(size_t)(tj + row) * SD + k] : 0.f;
        }
        __syncthreads();
        #pragma unroll 16
        for (int q = 0; q < 64; q++) acc += shi[li][q] * shj[lj][q];
        __syncthreads();
    }
    int i = ti + li, j = tj + lj;
    g_gram[i * NB + j] = acc - (i == j ? 1.f : 0.f);
}

// ---- STFT: packed real FFT + bf16 split out + per-frame stats ----
__global__ void stft_kernel(const float* __restrict__ audio) {
    const int t = blockIdx.x, b = blockIdx.y, tid = threadIdx.x; // 128
    __shared__ float sre[256], sim[256];
    const float* xp = audio + (size_t)b * SEG + t * HOP;
    const float W0 = 2.f * PI_F / (float)NFFT;
    #pragma unroll
    for (int p = tid; p < 256; p += 128) {
        float2 v = *(const float2*)(xp + 2 * p);
        float w0 = 0.5f - 0.5f * __cosf(W0 * (float)(2 * p));
        float w1 = 0.5f - 0.5f * __cosf(W0 * (float)(2 * p + 1));
        int rix = __brev((unsigned)p) >> 24;
        sre[rix] = v.x * w0; sim[rix] = v.y * w1;
    }
    __syncthreads();
    #pragma unroll
    for (int s = 0; s < 8; s++) {
        int half = 1 << s, pos = tid & (half - 1);
        int i0 = ((tid >> s) << (s + 1)) + pos, i1 = i0 + half;
        float wi, wr; __sincosf(-PI_F * (float)pos / (float)half, &wi, &wr);
        float ar = sre[i0], ai = sim[i0], br = sre[i1], bi = sim[i1];
        float tr = br * wr - bi * wi, ti2 = br * wi + bi * wr;
        sre[i0] = ar + tr; sim[i0] = ai + ti2;
        sre[i1] = ar - tr; sim[i1] = ai - ti2;
        __syncthreads();
    }
    __nv_bfloat16* oh = g_spec_hi + (size_t)b * SDP + t * NFREQ;
    __nv_bfloat16* ol = g_spec_lo + (size_t)b * SDP + t * NFREQ;
    float ls = 0.f, l2 = 0.f;
    int k = tid;
    __nv_bfloat16 h, l;
    if (k == 0) {
        float re0 = sre[0], im0 = sim[0];
        float v0 = fabsf(re0 + im0), v1 = fabsf(re0 - im0);
        float vh = sqrtf(sre[128] * sre[128] + sim[128] * sim[128]);
        bsplit(v0, h, l); oh[0] = h; ol[0] = l;
        bsplit(v1, h, l); oh[256] = h; ol[256] = l;
        bsplit(vh, h, l); oh[128] = h; ol[128] = l;
        ls = v0 + v1 + vh; l2 = v0 * v0 + v1 * v1 + vh * vh;
    } else {
        int mk = 256 - k;
        float zr = sre[k], zi = sim[k], yr = sre[mk], yi = sim[mk];
        float er = 0.5f * (zr + yr), ei = 0.5f * (zi - yi);
        float orr = 0.5f * (zi + yi), oi = -0.5f * (zr - yr);
        float ci, cr; __sincosf(-PI_F * (float)k / 256.f, &ci, &cr);
        float xr = er + cr * orr - ci * oi;
        float xi = ei + cr * oi + ci * orr;
        float va = sqrtf(xr * xr + xi * xi);
        float xr2 = er - cr * orr + ci * oi;
        float xi2 = -ei + cr * oi + ci * orr;
        float vb = sqrtf(xr2 * xr2 + xi2 * xi2);
        bsplit(va, h, l); oh[k] = h; ol[k] = l;
        bsplit(vb, h, l); oh[mk] = h; ol[mk] = l;
        ls = va + vb; l2 = va * va + vb * vb;
    }
    __syncthreads();
    sre[tid] = ls; sim[tid] = l2;
    __syncthreads();
    for (int o = 64; o > 0; o >>= 1) {
        if (tid < o) { sre[tid] += sre[tid + o]; sim[tid] += sim[tid + o]; }
        __syncthreads();
    }
    if (tid == 0) {
        g_fstat[((size_t)b * NFRM + t) * 2] = sre[0];
        g_fstat[((size_t)b * NFRM + t) * 2 + 1] = sim[0];
    }
}

// ---- finalize stats + zero K-pad ----
__global__ void finalize_kernel() {
    int b = blockIdx.x, tid = threadIdx.x; // 64
    if (tid >= 17) {
        size_t k = (size_t)b * SDP + SD + (tid - 17);
        g_spec_hi[k] = __float2bfloat16(0.f);
        g_spec_lo[k] = __float2bfloat16(0.f);
    }
    __shared__ float s1[17], s2[17];
    if (tid < 17) {
        s1[tid] = g_fstat[((size_t)b * NFRM + tid) * 2];
        s2[tid] = g_fstat[((size_t)b * NFRM + tid) * 2 + 1];
    }
    __syncthreads();
    if (tid == 0) {
        float a = 0.f, c = 0.f;
        #pragma unroll
        for (int i = 0; i < 17; i++) { a += s1[i]; c += s2[i]; }
        float mean = a / (float)SD;
        float var = (c - (float)SD * mean * mean) / (float)(SD - 1);
        g_stats[2 * b] = mean;
        g_stats[2 * b + 1] = 1.f / (sqrtf(fmaxf(var, 0.f)) + 1e-8f);
    }
}

// ---- bgemm: b = spec @ Dp^T via mma.sync bf16x3; 128 CTAs x (64M,128N) ----
#define AS 72            // smem row stride (bf16)
#define OAh 0
#define OAl 9216
#define OBh 18432
#define OBl 36864
__global__ void __launch_bounds__(256) bgemm_mma() {
    extern __shared__ char sm[];
    int tid = threadIdx.x, w = tid >> 5, lane = tid & 31;
    int g = lane >> 2, tg = lane & 3;
    int s0 = blockIdx.x * 64;
    int wm = w & 1, wn = w >> 1;          // warp tile: 32M x 32N
    int m0 = wm * 32, n0 = wn * 32;

    float acc[2][4][4] = {};
    uint4 pf[12];

    // chunk loaders
    auto gload = [&](int ch) {
        #pragma unroll
        for (int i = 0; i < 2; i++) {
            int e = tid + i * 256, row = e >> 3, u = e & 7;
            size_t go = (size_t)(s0 + row) * SDP + ch * 64 + u * 8;
            pf[i]     = *(const uint4*)(g_spec_hi + go);
            pf[2 + i] = *(const uint4*)(g_spec_lo + go);
        }
        #pragma unroll
        for (int i = 0; i < 4; i++) {
            int e = tid + i * 256, row = e >> 3, u = e & 7;
            size_t go = (size_t)row * SDP + ch * 64 + u * 8;
            pf[4 + i] = *(const uint4*)(g_Dp_hi + go);
            pf[8 + i] = *(const uint4*)(g_Dp_lo + go);
        }
    };
    auto sstore = [&]() {
        #pragma unroll
        for (int i = 0; i < 2; i++) {
            int e = tid + i * 256, row = e >> 3, u = e & 7;
            int off = (row * AS + u * 8) * 2;
            *(uint4*)(sm + OAh + off) = pf[i];
            *(uint4*)(sm + OAl + off) = pf[2 + i];
        }
        #pragma unroll
        for (int i = 0; i < 4; i++) {
            int e = tid + i * 256, row = e >> 3, u = e & 7;
            int off = (row * AS + u * 8) * 2;
            *(uint4*)(sm + OBh + off) = pf[4 + i];
            *(uint4*)(sm + OBl + off) = pf[8 + i];
        }
    };

    gload(0); sstore(); __syncthreads();
    for (int ch = 0; ch < NCH; ch++) {
        if (ch + 1 < NCH) gload(ch + 1);
        #pragma unroll
        for (int ks = 0; ks < 4; ks++) {
            int k0 = ks * 16 + tg * 2;
            uint32_t ah[2][4], al[2][4], bh[4][2], bl[4][2];
            #pragma unroll
            for (int mt = 0; mt < 2; mt++) {
                int base = ((m0 + mt * 16 + g) * AS + k0) * 2;
                ah[mt][0] = lds32(sm + OAh + base);
                ah[mt][1] = lds32(sm + OAh + base + 8 * AS * 2);
                ah[mt][2] = lds32(sm + OAh + base + 16);
                ah[mt][3] = lds32(sm + OAh + base + 8 * AS * 2 + 16);
                al[mt][0] = lds32(sm + OAl + base);
                al[mt][1] = lds32(sm + OAl + base + 8 * AS * 2);
                al[mt][2] = lds32(sm + OAl + base + 16);
                al[mt][3] = lds32(sm + OAl + base + 8 * AS * 2 + 16);
            }
            #pragma unroll
            for (int nt = 0; nt < 4; nt++) {
                int base = ((n0 + nt * 8 + g) * AS + k0) * 2;
                bh[nt][0] = lds32(sm + OBh + base);
                bh[nt][1] = lds32(sm + OBh + base + 16);
                bl[nt][0] = lds32(sm + OBl + base);
                bl[nt][1] = lds32(sm + OBl + base + 16);
            }
            #pragma unroll
            for (int mt = 0; mt < 2; mt++)
                #pragma unroll
                for (int nt = 0; nt < 4; nt++) {
                    mma16816(acc[mt][nt], ah[mt], bh[nt]);
                    mma16816(acc[mt][nt], al[mt], bh[nt]);
                    mma16816(acc[mt][nt], ah[mt], bl[nt]);
                }
        }
        __syncthreads();
        if (ch + 1 < NCH) { sstore(); __syncthreads(); }
    }

    // epilogue with normalization folded in
    #pragma unroll
    for (int mt = 0; mt < 2; mt++) {
        int r0 = s0 + m0 + mt * 16 + g;
        float me0 = g_stats[2 * r0],       iv0 = g_stats[2 * r0 + 1];
        float me1 = g_stats[2 * (r0 + 8)], iv1 = g_stats[2 * (r0 + 8) + 1];
        #pragma unroll
        for (int nt = 0; nt < 4; nt++) {
            int c = n0 + nt * 8 + tg * 2;
            float sd0 = g_sumD[c], sd1 = g_sumD[c + 1];
            float2 v0 = { (acc[mt][nt][0] - me0 * sd0) * iv0,
                          (acc[mt][nt][1] - me0 * sd1) * iv0 };
            float2 v1 = { (acc[mt][nt][2] - me1 * sd0) * iv1,
                          (acc[mt][nt][3] - me1 * sd1) * iv1 };
            *(float2*)(g_b + (size_t)r0 * NB + c) = v0;
            *(float2*)(g_b + (size_t)(r0 + 8) * NB + c) = v1;
        }
    }
}

// ---- LCA: 50 iters mma.sync bf16x3 vs resident gram; 128 CTAs x 64 samples ----
#define GS 136
#define OGh 0
#define OGl 34816
#define OSh 69632
#define OSl 87040
__global__ void __launch_bounds__(256) lca_mma(float* __restrict__ out) {
    extern __shared__ char sm[];
    int tid = threadIdx.x, w = tid >> 5, lane = tid & 31;
    int g = lane >> 2, tg = lane & 3;
    int s0 = blockIdx.x * 64;
    int wm = w & 1, wn = w >> 1;
    int m0 = wm * 32, n0 = wn * 32;

    // gram -> SMEM bf16 hi/lo
    for (int idx = tid; idx < NB * NB; idx += 256) {
        int j = idx >> 7, k = idx & 127;
        __nv_bfloat16 h, l; bsplit(g_gram[idx], h, l);
        int off = (j * GS + k) * 2;
        *(__nv_bfloat16*)(sm + OGh + off) = h;
        *(__nv_bfloat16*)(sm + OGl + off) = l;
    }

    float u[2][4][4] = {}, bb[2][4][4];
    #pragma unroll
    for (int mt = 0; mt < 2; mt++) {
        int r0 = s0 + m0 + mt * 16 + g;
        #pragma unroll
        for (int nt = 0; nt < 4; nt++) {
            int c = n0 + nt * 8 + tg * 2;
            float2 v0 = *(const float2*)(g_b + (size_t)r0 * NB + c);
            float2 v1 = *(const float2*)(g_b + (size_t)(r0 + 8) * NB + c);
            bb[mt][nt][0] = v0.x; bb[mt][nt][1] = v0.y;
            bb[mt][nt][2] = v1.x; bb[mt][nt][3] = v1.y;
        }
    }
    __syncthreads();

    for (int it = 0; it < ITERS; it++) {
        // a = softshrink(u) -> SMEM bf16 hi/lo in fragment layout
        #pragma unroll
        for (int mt = 0; mt < 2; mt++) {
            int r0 = m0 + mt * 16 + g;
            #pragma unroll
            for (int nt = 0; nt < 4; nt++) {
                int c = n0 + nt * 8 + tg * 2;
                __nv_bfloat16 h0, l0, h1, l1, h2, l2, h3, l3;
                bsplit(sshrink(u[mt][nt][0]), h0, l0);
                bsplit(sshrink(u[mt][nt][1]), h1, l1);
                bsplit(sshrink(u[mt][nt][2]), h2, l2);
                bsplit(sshrink(u[mt][nt][3]), h3, l3);
                int o0 = (r0 * GS + c) * 2, o1 = ((r0 + 8) * GS + c) * 2;
                *(uint32_t*)(sm + OSh + o0) = bpack(h0, h1);
                *(uint32_t*)(sm + OSl + o0) = bpack(l0, l1);
                *(uint32_t*)(sm + OSh + o1) = bpack(h2, h3);
                *(uint32_t*)(sm + OSl + o1) = bpack(l2, l3);
            }
        }
        __syncthreads();

        float acc[2][4][4] = {};
        #pragma unroll
        for (int ks = 0; ks < 8; ks++) {
            int k0 = ks * 16 + tg * 2;
            uint32_t ah[2][4], al[2][4], bh[4][2], bl[4][2];
            #pragma unroll
            for (int mt = 0; mt < 2; mt++) {
                int base = ((m0 + mt * 16 + g) * GS + k0) * 2;
                ah[mt][0] = lds32(sm + OSh + base);
                ah[mt][1] = lds32(sm + OSh + base + 8 * GS * 2);
                ah[mt][2] = lds32(sm + OSh + base + 16);
                ah[mt][3] = lds32(sm + OSh + base + 8 * GS * 2 + 16);
                al[mt][0] = lds32(sm + OSl + base);
                al[mt][1] = lds32(sm + OSl + base + 8 * GS * 2);
                al[mt][2] = lds32(sm + OSl + base + 16);
                al[mt][3] = lds32(sm + OSl + base + 8 * GS * 2 + 16);
            }
            #pragma unroll
            for (int nt = 0; nt < 4; nt++) {
                int base = ((n0 + nt * 8 + g) * GS + k0) * 2;
                bh[nt][0] = lds32(sm + OGh + base);
                bh[nt][1] = lds32(sm + OGh + base + 16);
                bl[nt][0] = lds32(sm + OGl + base);
                bl[nt][1] = lds32(sm + OGl + base + 16);
            }
            #pragma unroll
            for (int mt = 0; mt < 2; mt++)
                #pragma unroll
                for (int nt = 0; nt < 4; nt++) {
                    mma16816(acc[mt][nt], ah[mt], bh[nt]);
                    mma16816(acc[mt][nt], al[mt], bh[nt]);
                    mma16816(acc[mt][nt], ah[mt], bl[nt]);
                }
        }
        #pragma unroll
        for (int mt = 0; mt < 2; mt++)
            #pragma unroll
            for (int nt = 0; nt < 4; nt++)
                #pragma unroll
                for (int q = 0; q < 4; q++)
                    u[mt][nt][q] += (bb[mt][nt][q] - u[mt][nt][q] - acc[mt][nt][q]) * 0.1f;
        __syncthreads();
    }

    #pragma unroll
    for (int mt = 0; mt < 2; mt++) {
        int r0 = s0 + m0 + mt * 16 + g;
        #pragma unroll
        for (int nt = 0; nt < 4; nt++) {
            int c = n0 + nt * 8 + tg * 2;
            float2 v0 = { sshrink(u[mt][nt][0]), sshrink(u[mt][nt][1]) };
            float2 v1 = { sshrink(u[mt][nt][2]), sshrink(u[mt][nt][3]) };
            *(float2*)(out + (size_t)r0 * NB + c) = v0;
            *(float2*)(out + (size_t)(r0 + 8) * NB + c) = v1;
        }
    }
}

// ---- launch ----
extern "C" void kernel_launch(void* const* d_in, const int* in_sizes, int n_in,
                              void* d_out, int out_size) {
    const float* audio = (const float*)d_in[0];
    const float* D     = (const float*)d_in[1];
    float* out = (float*)d_out;
    static const int BG_SMEM = 55296;
    static const int LCA_SMEM = 104448;
    cudaFuncSetAttribute(bgemm_mma, cudaFuncAttributeMaxDynamicSharedMemorySize, BG_SMEM);
    cudaFuncSetAttribute(lca_mma, cudaFuncAttributeMaxDynamicSharedMemorySize, LCA_SMEM);

    permuted_kernel<<<NB, 256>>>(D);
    gram_kernel<<<64, 256>>>(D);
    stft_kernel<<<dim3(NFRM, BATCH), 128>>>(audio);
    finalize_kernel<<<BATCH, 64>>>();
    bgemm_mma<<<BATCH / 64, 256, BG_SMEM>>>();
    lca_mma<<<BATCH / 64, 256, LCA_SMEM>>>(out);
}